// round 4
// baseline (speedup 1.0000x reference)
#include <cuda_runtime.h>
#include <math.h>

#define LF 104          // node feature length
#define SS 500          // sink outputs / classes
#define MM 64           // molecules
#define TT 32           // topological levels
#define WW 256          // nodes per level
#define NROWS (MM*WW)   // 16384
#define RT 128          // rows per CTA
#define NTHR 416        // 16 ty x 26 tx = 13 warps
#define KC 26           // K chunk
#define NW4 (KC*LF/4)   // weight float4 per chunk = 676
#define NI2 (RT*KC/2)   // input float2 per chunk = 1664 = 4*NTHR

__device__ float g_hA[NROWS*LF];
__device__ float g_hB[NROWS*LF];
__device__ float g_sink[MM*SS];

typedef unsigned long long u64;

__device__ __forceinline__ u64 dup2(float x){
    u64 r; asm("mov.b64 %0, {%1, %1};" : "=l"(r) : "f"(x)); return r;
}
__device__ __forceinline__ void fma2(u64 &d, u64 a, u64 b){
    asm("fma.rn.f32x2 %0, %1, %2, %0;" : "+l"(d) : "l"(a), "l"(b));
}
__device__ __forceinline__ float2 unpack2(u64 a){
    float2 v; asm("mov.b64 {%0, %1}, %2;" : "=f"(v.x), "=f"(v.y) : "l"(a)); return v;
}

// Unified level kernel.
//  t == 0: nchunk = 4,  Wm = W_single [104,104], input = context[:,0]
//  t >= 1: nchunk = 12, Wm = W_int2  [312,104], input = [ctx | par0 | par1]
// chunk c: segment sg = c>>2 (0 ctx, 1 parent0, 2 parent1), koff = (c&3)*KC.
__global__ void __launch_bounds__(NTHR, 1) level_kernel(
    const float* __restrict__ ctx, const int* __restrict__ pidx,
    const float* __restrict__ Wm, const float* __restrict__ bias,
    int t, int nchunk)
{
    __shared__ float sIn[KC*RT];   // 13312 B, natural: sIn[k*RT + r]
    __shared__ u64   sWd[KC*LF];   // 21632 B, duplicated weights: sWd[k*LF + c]

    const float* hsrc = (t & 1) ? g_hA : g_hB;
    float*       hdst = (t & 1) ? g_hB : g_hA;

    const int tid = threadIdx.x;
    const int ty = tid & 15;       // row group: 8 rows as pairs {ty+16j}, j=0..3
    const int tx = tid >> 4;       // col group: cols tx*4..tx*4+3 (tx 0..25)
    const int rbase = blockIdx.x * RT;

    u64 acc[4][4];                 // [rowpair j][col c]; lanes = (even row, odd row)
    #pragma unroll
    for (int j = 0; j < 4; ++j)
        #pragma unroll
        for (int c = 0; c < 4; ++c) acc[j][c] = 0ULL;

    float4 wpre[2];
    float2 ipre[4];

    // ---- LDG chunk c into registers ----
    auto load_chunk = [&](int c) {
        const int koff = (c & 3) * KC;
        const int sg = c >> 2;
        const float4* wsrc = (const float4*)(Wm + (size_t)c*KC*LF);
        #pragma unroll
        for (int j = 0; j < 2; ++j) {
            int idx = tid + j*NTHR;
            if (idx < NW4) wpre[j] = wsrc[idx];
        }
        #pragma unroll
        for (int j = 0; j < 4; ++j) {
            int idx = tid + j*NTHR;          // 0..1663
            int r = idx & (RT-1);
            int q = idx >> 7;                // 0..12 (float2 within chunk)
            int grow = rbase + r;
            int m = grow >> 8, w = grow & 255;
            const float* src;
            if (sg == 0) {
                src = ctx + (((size_t)m*TT + t)*WW + w)*LF + koff + q*2;
            } else {
                int p = pidx[(((size_t)m*(TT-1) + (t-1))*WW + w)*2 + (sg-1)];
                src = hsrc + ((size_t)m*WW + p)*LF + koff + q*2;
            }
            ipre[j] = *(const float2*)src;
        }
    };

    // ---- registers -> smem ----
    auto store_chunk = [&]() {
        #pragma unroll
        for (int j = 0; j < 2; ++j) {
            int idx = tid + j*NTHR;
            if (idx < NW4) {
                int k = idx / 26, cq = idx % 26;
                u64* d = &sWd[k*LF + cq*4];
                d[0] = dup2(wpre[j].x); d[1] = dup2(wpre[j].y);
                d[2] = dup2(wpre[j].z); d[3] = dup2(wpre[j].w);
            }
        }
        #pragma unroll
        for (int j = 0; j < 4; ++j) {
            int idx = tid + j*NTHR;
            int r = idx & (RT-1);
            int q = idx >> 7;
            sIn[(q*2  )*RT + r] = ipre[j].x;
            sIn[(q*2+1)*RT + r] = ipre[j].y;
        }
    };

    load_chunk(0);
    for (int c = 0; c < nchunk; ++c) {
        store_chunk();
        __syncthreads();
        if (c + 1 < nchunk) load_chunk(c + 1);

        // ---- compute: 8 rows (4 lane-pairs) x 4 cols per thread ----
        #pragma unroll 2
        for (int k = 0; k < KC; ++k) {
            const ulonglong2* wk = (const ulonglong2*)&sWd[k*LF + tx*4];
            ulonglong2 w01 = wk[0];
            ulonglong2 w23 = wk[1];
            const u64* ik = (const u64*)&sIn[k*RT];
            u64 a0 = ik[ty     ];
            u64 a1 = ik[ty + 16];
            u64 a2 = ik[ty + 32];
            u64 a3 = ik[ty + 48];
            fma2(acc[0][0], a0, w01.x); fma2(acc[0][1], a0, w01.y);
            fma2(acc[0][2], a0, w23.x); fma2(acc[0][3], a0, w23.y);
            fma2(acc[1][0], a1, w01.x); fma2(acc[1][1], a1, w01.y);
            fma2(acc[1][2], a1, w23.x); fma2(acc[1][3], a1, w23.y);
            fma2(acc[2][0], a2, w01.x); fma2(acc[2][1], a2, w01.y);
            fma2(acc[2][2], a2, w23.x); fma2(acc[2][3], a2, w23.y);
            fma2(acc[3][0], a3, w01.x); fma2(acc[3][1], a3, w01.y);
            fma2(acc[3][2], a3, w23.x); fma2(acc[3][3], a3, w23.y);
        }
        __syncthreads();
    }

    // ---- epilogue: + bias, ReLU, store (2 rows per acc group) ----
    float4 bv = *(const float4*)&bias[tx*4];
    #pragma unroll
    for (int j = 0; j < 4; ++j) {
        float2 v0 = unpack2(acc[j][0]);
        float2 v1 = unpack2(acc[j][1]);
        float2 v2 = unpack2(acc[j][2]);
        float2 v3 = unpack2(acc[j][3]);
        float4 oe = make_float4(fmaxf(v0.x + bv.x, 0.f), fmaxf(v1.x + bv.y, 0.f),
                                fmaxf(v2.x + bv.z, 0.f), fmaxf(v3.x + bv.w, 0.f));
        float4 oo = make_float4(fmaxf(v0.y + bv.x, 0.f), fmaxf(v1.y + bv.y, 0.f),
                                fmaxf(v2.y + bv.z, 0.f), fmaxf(v3.y + bv.w, 0.f));
        size_t r0 = (size_t)rbase + 2*(ty + 16*j);
        *(float4*)&hdst[r0*LF + tx*4]     = oe;
        *(float4*)&hdst[(r0+1)*LF + tx*4] = oo;
    }
}

// Sink: sink_out[m,s] = dot(concat_{j<7} h_last[m, sidx[m,j], :], W_sink7[:, s])
__global__ void __launch_bounds__(128) sink_kernel(
    const int* __restrict__ sidx, const float* __restrict__ Wk)
{
    __shared__ float sh[7*LF];
    const int m = blockIdx.x;
    const int tid = threadIdx.x;
    const float* h = g_hB;   // level 31 output lives in g_hB (31 is odd)

    for (int idx = tid; idx < 7*LF; idx += 128) {
        int j = idx / LF, l = idx % LF;
        int p = sidx[m*7 + j];
        sh[idx] = h[((size_t)m*WW + p)*LF + l];
    }
    __syncthreads();

    int s = blockIdx.y * 128 + tid;
    if (s < SS) {
        float acc = 0.f;
        #pragma unroll 8
        for (int kk = 0; kk < 7*LF; ++kk)
            acc = fmaf(sh[kk], Wk[(size_t)kk*SS + s], acc);
        g_sink[(size_t)m*SS + s] = acc;
    }
}

// Final head: avg over molecules + b_sink7, 500x500 matvec + b_cls, sigmoid.
__global__ void __launch_bounds__(512) final_kernel(
    const float* __restrict__ bs, const float* __restrict__ Wc,
    const float* __restrict__ bc, float* __restrict__ out)
{
    __shared__ float avg[SS];
    const int tid = threadIdx.x;
    for (int s = tid; s < SS; s += 512) {
        float a = 0.f;
        #pragma unroll 8
        for (int m = 0; m < MM; ++m) a += g_sink[(size_t)m*SS + s];
        avg[s] = a * (1.0f/MM) + bs[s];
    }
    __syncthreads();
    for (int s = tid; s < SS; s += 512) {
        float acc = bc[s];
        #pragma unroll 4
        for (int i = 0; i < SS; ++i)
            acc = fmaf(avg[i], Wc[(size_t)i*SS + s], acc);
        out[s] = 1.0f / (1.0f + expf(-acc));
    }
}

extern "C" void kernel_launch(void* const* d_in, const int* in_sizes, int n_in,
                              void* d_out, int out_size)
{
    const float* ctx      = (const float*)d_in[0];
    const int*   pidx     = (const int*)  d_in[1];
    const int*   sidx     = (const int*)  d_in[2];
    const float* W_single = (const float*)d_in[3];
    const float* b_single = (const float*)d_in[4];
    const float* W_int2   = (const float*)d_in[5];
    const float* b_int2   = (const float*)d_in[6];
    const float* W_sink7  = (const float*)d_in[7];
    const float* b_sink7  = (const float*)d_in[8];
    const float* W_cls    = (const float*)d_in[9];
    const float* b_cls    = (const float*)d_in[10];
    float* out = (float*)d_out;

    dim3 grid(NROWS / RT);   // 128 CTAs, single wave

    level_kernel<<<grid, NTHR>>>(ctx, pidx, W_single, b_single, 0, 4);
    for (int t = 1; t < TT; ++t)
        level_kernel<<<grid, NTHR>>>(ctx, pidx, W_int2, b_int2, t, 12);
    sink_kernel<<<dim3(MM, (SS + 127) / 128), 128>>>(sidx, W_sink7);
    final_kernel<<<1, 512>>>(b_sink7, W_cls, b_cls, out);
}